// round 13
// baseline (speedup 1.0000x reference)
#include <cuda_runtime.h>
#include <math.h>
#include <stdint.h>

// Problem constants
#define BB 4
#define NN 256
#define TOK (BB*NN)        // 1024
#define OBSD 64
#define QDIM 32
#define HH 256
#define DD 128
#define NOPS 8
#define QE 64

// Output layout
#define EDGE_OFF 0
#define OP_OFF   (TOK*NN)                 // 262144
#define NEXT_OFF (OP_OFF + TOK*NN*NOPS)   // 2359296

// Scratch
__device__ float g_lat[TOK * DD];
__device__ float g_EA[TOK * HH];
__device__ float g_EB[TOK * HH];
__device__ float g_OA[TOK * HH];
__device__ float g_OB[TOK * HH];

// ---------------------------------------------------------------------------
// helpers
// ---------------------------------------------------------------------------
__device__ __forceinline__ uint32_t f2tf32(float f) {
    uint32_t r;
    asm("cvt.rna.tf32.f32 %0, %1;" : "=r"(r) : "f"(f));
    return r;
}
__device__ __forceinline__ void mma8(float* c, uint32_t a0, uint32_t a1,
                                     uint32_t a2, uint32_t a3,
                                     uint32_t b0, uint32_t b1) {
    asm volatile(
        "mma.sync.aligned.m16n8k8.row.col.f32.tf32.tf32.f32 "
        "{%0,%1,%2,%3}, {%4,%5,%6,%7}, {%8,%9}, {%0,%1,%2,%3};"
        : "+f"(c[0]), "+f"(c[1]), "+f"(c[2]), "+f"(c[3])
        : "r"(a0), "r"(a1), "r"(a2), "r"(a3), "r"(b0), "r"(b1));
}
__device__ __forceinline__ float qreduce(float v) {   // sum across tg (quad)
    v += __shfl_xor_sync(0xFFFFFFFF, v, 1);
    v += __shfl_xor_sync(0xFFFFFFFF, v, 2);
    return v;
}

// ---------------------------------------------------------------------------
// Kernel 1: per-token pipeline, 8 tokens/block (unchanged; proven).
// ---------------------------------------------------------------------------
#define S_OBS   0
#define S_LATIN (S_OBS+512)
#define S_Q     (S_LATIN+1024)
#define S_H1    (S_Q+256)
#define S_NE    (S_H1+2048)
#define S_UPD   (S_NE+2048)
#define S_GI    (S_UPD+1024)
#define S_GH    (S_GI+3072)
#define S_LAT   (S_GH+3072)
#define S_QE    (S_LAT+1024)
#define S_HID   (S_QE+512)
#define S_RED   (S_HID+2048)
#define SM1_FLOATS (S_RED+256)

__global__ void __launch_bounds__(256)
tok_kernel(const float* __restrict__ obs, const float* __restrict__ latent,
           const float* __restrict__ query,
           const float* __restrict__ enc_w1, const float* __restrict__ enc_b1,
           const float* __restrict__ enc_w2, const float* __restrict__ enc_b2,
           const float* __restrict__ upd_w,  const float* __restrict__ upd_b,
           const float* __restrict__ gru_wi, const float* __restrict__ gru_bi,
           const float* __restrict__ gru_wh, const float* __restrict__ gru_bh,
           const float* __restrict__ eh_w1,  const float* __restrict__ eh_b1,
           const float* __restrict__ oh_w1,  const float* __restrict__ oh_b1,
           const float* __restrict__ q_w,    const float* __restrict__ q_b,
           const float* __restrict__ nh_w1,  const float* __restrict__ nh_b1,
           const float* __restrict__ nh_w2,  const float* __restrict__ nh_b2,
           float* __restrict__ out)
{
    extern __shared__ float sm[];
    const int tid = threadIdx.x;
    const int t0  = blockIdx.x * 8;

    for (int idx = tid; idx < 8*OBSD; idx += 256) sm[S_OBS+idx]   = obs[(size_t)t0*OBSD + idx];
    for (int idx = tid; idx < 8*DD;   idx += 256) sm[S_LATIN+idx] = latent[(size_t)t0*DD + idx];
    sm[S_Q + tid] = query[(size_t)t0*QDIM + tid];
    __syncthreads();

    {
        float acc[8];
        float b = enc_b1[tid];
        #pragma unroll
        for (int t = 0; t < 8; t++) acc[t] = b;
        for (int k = 0; k < OBSD; k++) {
            float w = enc_w1[k*HH + tid];
            #pragma unroll
            for (int t = 0; t < 8; t++) acc[t] = fmaf(sm[S_OBS + t*OBSD + k], w, acc[t]);
        }
        #pragma unroll
        for (int t = 0; t < 8; t++) sm[S_H1 + t*HH + tid] = fmaxf(acc[t], 0.0f);
    }
    __syncthreads();

    {
        float acc[8];
        float b = enc_b2[tid];
        #pragma unroll
        for (int t = 0; t < 8; t++) acc[t] = b;
        for (int k = 0; k < HH; k++) {
            float w = enc_w2[k*HH + tid];
            #pragma unroll
            for (int t = 0; t < 8; t++) acc[t] = fmaf(sm[S_H1 + t*HH + k], w, acc[t]);
        }
        #pragma unroll
        for (int t = 0; t < 8; t++) sm[S_NE + t*HH + tid] = fmaxf(acc[t], 0.0f);
    }
    __syncthreads();

    if (tid < DD) {
        float acc[8];
        float b = upd_b[tid];
        #pragma unroll
        for (int t = 0; t < 8; t++) acc[t] = b;
        for (int k = 0; k < HH; k++) {
            float w = upd_w[k*DD + tid];
            #pragma unroll
            for (int t = 0; t < 8; t++) acc[t] = fmaf(sm[S_NE + t*HH + k], w, acc[t]);
        }
        #pragma unroll
        for (int t = 0; t < 8; t++) sm[S_UPD + t*DD + tid] = acc[t];
    }
    __syncthreads();

    for (int o = tid; o < 3*DD; o += 256) {
        float ai[8], ah[8];
        float bi_ = gru_bi[o], bh_ = gru_bh[o];
        #pragma unroll
        for (int t = 0; t < 8; t++) { ai[t] = bi_; ah[t] = bh_; }
        for (int k = 0; k < DD; k++) {
            float wi = gru_wi[k*(3*DD) + o];
            float wh = gru_wh[k*(3*DD) + o];
            #pragma unroll
            for (int t = 0; t < 8; t++) {
                ai[t] = fmaf(sm[S_UPD   + t*DD + k], wi, ai[t]);
                ah[t] = fmaf(sm[S_LATIN + t*DD + k], wh, ah[t]);
            }
        }
        #pragma unroll
        for (int t = 0; t < 8; t++) { sm[S_GI + t*(3*DD) + o] = ai[t]; sm[S_GH + t*(3*DD) + o] = ah[t]; }
    }
    __syncthreads();

    for (int idx = tid; idx < 8*DD; idx += 256) {
        int t = idx >> 7, d = idx & 127;
        float ir = sm[S_GI + t*(3*DD) + d],        hr = sm[S_GH + t*(3*DD) + d];
        float iz = sm[S_GI + t*(3*DD) + DD + d],   hz = sm[S_GH + t*(3*DD) + DD + d];
        float in_ = sm[S_GI + t*(3*DD) + 2*DD + d], hn = sm[S_GH + t*(3*DD) + 2*DD + d];
        float r = 1.0f / (1.0f + expf(-(ir + hr)));
        float z = 1.0f / (1.0f + expf(-(iz + hz)));
        float nh = tanhf(in_ + r * hn);
        float li = sm[S_LATIN + t*DD + d];
        float l  = (1.0f - z) * nh + z * li;
        sm[S_LAT + t*DD + d] = l;
        g_lat[(size_t)(t0 + t)*DD + d] = l;
    }

    if (tid < QE) {
        float acc[8];
        float b = q_b[tid];
        #pragma unroll
        for (int t = 0; t < 8; t++) acc[t] = b;
        for (int k = 0; k < QDIM; k++) {
            float w = q_w[k*QE + tid];
            #pragma unroll
            for (int t = 0; t < 8; t++) acc[t] = fmaf(sm[S_Q + t*QDIM + k], w, acc[t]);
        }
        #pragma unroll
        for (int t = 0; t < 8; t++) sm[S_QE + t*QE + tid] = fmaxf(acc[t], 0.0f);
    }
    __syncthreads();

    {
        float ea[8], eb[8], oa[8], ob[8];
        float be = eh_b1[tid], bo = oh_b1[tid];
        #pragma unroll
        for (int t = 0; t < 8; t++) { ea[t] = be; eb[t] = 0.f; oa[t] = bo; ob[t] = 0.f; }
        for (int k = 0; k < DD; k++) {
            float wel = eh_w1[k*HH + tid];
            float wer = eh_w1[(DD + k)*HH + tid];
            float wol = oh_w1[k*HH + tid];
            float wor = oh_w1[(DD + k)*HH + tid];
            #pragma unroll
            for (int t = 0; t < 8; t++) {
                float lv = sm[S_LAT + t*DD + k];
                ea[t] = fmaf(lv, wel, ea[t]);
                eb[t] = fmaf(lv, wer, eb[t]);
                oa[t] = fmaf(lv, wol, oa[t]);
                ob[t] = fmaf(lv, wor, ob[t]);
            }
        }
        #pragma unroll
        for (int t = 0; t < 8; t++) {
            size_t p = (size_t)(t0 + t)*HH + tid;
            g_EA[p] = ea[t]; g_EB[p] = eb[t]; g_OA[p] = oa[t]; g_OB[p] = ob[t];
        }
    }

    {
        float acc[8];
        float b = nh_b1[tid];
        #pragma unroll
        for (int t = 0; t < 8; t++) acc[t] = b;
        for (int k = 0; k < DD; k++) {
            float w = nh_w1[k*HH + tid];
            #pragma unroll
            for (int t = 0; t < 8; t++) acc[t] = fmaf(sm[S_LAT + t*DD + k], w, acc[t]);
        }
        for (int k = 0; k < HH; k++) {
            float w = nh_w1[(DD + k)*HH + tid];
            #pragma unroll
            for (int t = 0; t < 8; t++) acc[t] = fmaf(sm[S_NE + t*HH + k], w, acc[t]);
        }
        for (int k = 0; k < QE; k++) {
            float w = nh_w1[(DD + HH + k)*HH + tid];
            #pragma unroll
            for (int t = 0; t < 8; t++) acc[t] = fmaf(sm[S_QE + t*QE + k], w, acc[t]);
        }
        #pragma unroll
        for (int t = 0; t < 8; t++) sm[S_HID + t*HH + tid] = fmaxf(acc[t], 0.0f);
    }
    __syncthreads();

    for (int t = 0; t < 8; t++) {
        sm[S_RED + tid] = sm[S_HID + t*HH + tid] * nh_w2[tid];
        __syncthreads();
        for (int s = 128; s > 0; s >>= 1) {
            if (tid < s) sm[S_RED + tid] += sm[S_RED + tid + s];
            __syncthreads();
        }
        if (tid == 0) out[NEXT_OFF + t0 + t] = sm[S_RED] + nh_b2[0];
        __syncthreads();
    }
}

// ---------------------------------------------------------------------------
// Kernel 2: persistent tf32 mma.sync pair kernel, 512 threads.
// 148 CTAs. CTAs [0,66) = edge head, [66,148) = op head.
// 16 warps: wj = wid&1 (j half of 64), wh = wid>>1 (h block of 32).
// Each warp: 64j x 32h via mma.m16n8k8 (c[4][4][4] = 64 regs).
// Fragment-pair-permuted k layout: within each group of 8 k, value kin sits at
// slot m(kin) = (kin&3)*2 + (kin>>2), so (tg, tg+4) pairs are adjacent words
// -> conflict-free ld.shared.v2 for both A and B fragments.
// ---------------------------------------------------------------------------
#define DSTRIDE 136                   // words/row (136 % 32 == 8 -> cf v2 loads)
#define SB_D    0                     // 128*136*4 = 69632 B (aliased by partO)
#define SB_W    69632                 // 16*2048*4 = 131072 B  [ks][h*8+slot]
#define SB_W2   (SB_W + 131072)       // 200704: 2048 f
#define SB_EA   (SB_W2 + 8192)        // 208896: 256 f
#define SB_REDB (SB_EA + 1024)        // 209920: 1024 f (edge partials 8x128)
#define SB_LATI (SB_REDB + 4096)      // 214016: 128 f
#define SB_TOTAL (SB_LATI + 512)      // 214528 B

#define N_EDGE_CTAS 66
#define N_CTAS 148

__global__ void __launch_bounds__(512, 1)
pair_kernel(const float* __restrict__ eh_w1, const float* __restrict__ eh_w2,
            const float* __restrict__ eh_b2,
            const float* __restrict__ oh_w1, const float* __restrict__ oh_w2,
            const float* __restrict__ oh_b2,
            float* __restrict__ out)
{
    extern __shared__ char smraw[];
    uint32_t* dD    = (uint32_t*)(smraw + SB_D);
    uint32_t* dW    = (uint32_t*)(smraw + SB_W);
    float*    smW2  = (float*)(smraw + SB_W2);
    float*    smEA  = (float*)(smraw + SB_EA);
    float*    smRED = (float*)(smraw + SB_REDB);
    float*    smLAT = (float*)(smraw + SB_LATI);
    float*    partO = (float*)(smraw + SB_D);   // aliases D (dead after mainloop+sync)

    const int tid  = threadIdx.x;
    const int wid  = tid >> 5;      // 0..15
    const int lane = tid & 31;
    const int gid  = lane >> 2;     // 0..7
    const int tg   = lane & 3;      // 0..3
    const int wj   = wid & 1;       // j half
    const int wh   = wid >> 1;      // 0..7 : h block of 32
    const int j0   = wj * 64;
    const int h0   = wh * 32;

    int head, pos, npos;
    if (blockIdx.x < N_EDGE_CTAS) { head = 0; pos = blockIdx.x;               npos = N_EDGE_CTAS; }
    else                          { head = 1; pos = blockIdx.x - N_EDGE_CTAS; npos = N_CTAS - N_EDGE_CTAS; }

    // ---- stage W_abs (tf32, permuted) once per CTA ----
    {
        const float* Wsrc = (head ? oh_w1 : eh_w1) + (size_t)(2*DD)*HH;
        for (int idx = tid; idx < DD*HH; idx += 512) {
            int k = idx >> 8, h = idx & 255;
            dW[(k>>3)*2048 + h*8 + (k&3)*2 + ((k>>2)&1)] = f2tf32(Wsrc[idx]);
        }
        if (head == 0) { if (tid < 256) smW2[tid] = eh_w2[tid]; }
        else           { for (int idx = tid; idx < HH*NOPS; idx += 512) smW2[idx] = oh_w2[idx]; }
    }

    const float* XA = head ? g_OA : g_EA;
    const float* XB = head ? g_OB : g_EB;

    // per-lane D-build store slot: lane owns k = lane + 32q
    const int dslot = (lane >> 3)*8 + (lane & 3)*2 + ((lane >> 2) & 1);

    for (int g = pos; g < 2048; g += npos) {
        const int b = g >> 9, i = (g >> 1) & 255, jt = g & 1;
        const int ti = b*NN + i;
        const int jbase = b*NN + jt*128;

        __syncthreads();   // prev epilogue done before overwriting smEA/smLAT/D
        if (tid < 128) smLAT[tid] = g_lat[(size_t)ti*DD + tid];
        else if (tid >= 256 && tid < 512) smEA[tid - 256] = XA[(size_t)ti*HH + tid - 256];
        __syncthreads();

        // ---- build D[j][k] = tf32(|lat_i - lat_j|), permuted k layout ----
        {
            float li4[4];
            #pragma unroll
            for (int q = 0; q < 4; ++q) li4[q] = smLAT[lane + 32*q];
            #pragma unroll
            for (int jj = 0; jj < 8; ++jj) {
                int j = wid*8 + jj;
                const float* lrow = g_lat + (size_t)(jbase + j)*DD;
                uint32_t* dst = dD + j*DSTRIDE + dslot;
                #pragma unroll
                for (int q = 0; q < 4; ++q)
                    dst[q*32] = f2tf32(fabsf(li4[q] - lrow[lane + 32*q]));
            }
        }
        __syncthreads();

        // ---- mma phase: hidden[64j x 32h] per warp ----
        float c[4][4][4];
        #pragma unroll
        for (int mt = 0; mt < 4; ++mt)
            #pragma unroll
            for (int nt = 0; nt < 4; ++nt)
                #pragma unroll
                for (int q = 0; q < 4; ++q) c[mt][nt][q] = 0.0f;

        const uint32_t* Ab = dD + (j0 + gid)*DSTRIDE + 2*tg;
        const uint32_t* Bb = dW + (h0 + gid)*8 + 2*tg;

        #pragma unroll 4
        for (int ks = 0; ks < 16; ++ks) {
            uint2 av[4], aw[4], bv[4];
            #pragma unroll
            for (int mt = 0; mt < 4; ++mt) {
                av[mt] = *(const uint2*)(Ab + (mt*16)*DSTRIDE + ks*8);
                aw[mt] = *(const uint2*)(Ab + (mt*16+8)*DSTRIDE + ks*8);
            }
            #pragma unroll
            for (int nt = 0; nt < 4; ++nt)
                bv[nt] = *(const uint2*)(Bb + ks*2048 + nt*64);
            #pragma unroll
            for (int nt = 0; nt < 4; ++nt)
                #pragma unroll
                for (int mt = 0; mt < 4; ++mt)
                    mma8(c[mt][nt], av[mt].x, aw[mt].x, av[mt].y, aw[mt].y,
                         bv[nt].x, bv[nt].y);
        }
        __syncthreads();   // all warps done reading D before partO aliases it

        // ---- epilogue ----
        if (head == 0) {
            #pragma unroll
            for (int mt = 0; mt < 4; ++mt) {
                #pragma unroll
                for (int rh = 0; rh < 2; ++rh) {
                    int jl = j0 + mt*16 + gid + rh*8;
                    const float* ebrow = XB + (size_t)(jbase + jl)*HH;
                    float part = 0.0f;
                    #pragma unroll
                    for (int nt = 0; nt < 4; ++nt) {
                        int ha = h0 + nt*8 + 2*tg;
                        float2 eb = *(const float2*)(ebrow + ha);
                        float hv0 = fmaxf(c[mt][nt][rh*2+0] + smEA[ha]   + eb.x, 0.0f);
                        float hv1 = fmaxf(c[mt][nt][rh*2+1] + smEA[ha+1] + eb.y, 0.0f);
                        part = fmaf(hv0, smW2[ha],   part);
                        part = fmaf(hv1, smW2[ha+1], part);
                    }
                    part = qreduce(part);
                    if (tg == 0) smRED[wh*128 + jl] = part;
                }
            }
            __syncthreads();
            if (tid < 128) {
                float v = eh_b2[0];
                #pragma unroll
                for (int u = 0; u < 8; ++u) v += smRED[u*128 + tid];
                int jg = jt*128 + tid;
                if (jg == i) v = -8.0f;
                out[EDGE_OFF + (size_t)ti*NN + jg] = v;
            }
        } else {
            #pragma unroll
            for (int mt = 0; mt < 4; ++mt) {
                #pragma unroll
                for (int rh = 0; rh < 2; ++rh) {
                    int jl = j0 + mt*16 + gid + rh*8;
                    const float* obrow = XB + (size_t)(jbase + jl)*HH;
                    float po[8];
                    #pragma unroll
                    for (int k = 0; k < 8; ++k) po[k] = 0.0f;
                    #pragma unroll
                    for (int nt = 0; nt < 4; ++nt) {
                        int ha = h0 + nt*8 + 2*tg;
                        float2 ob = *(const float2*)(obrow + ha);
                        float hv0 = fmaxf(c[mt][nt][rh*2+0] + smEA[ha]   + ob.x, 0.0f);
                        float hv1 = fmaxf(c[mt][nt][rh*2+1] + smEA[ha+1] + ob.y, 0.0f);
                        const float* w0 = smW2 + ha*8;
                        const float* w1 = smW2 + (ha+1)*8;
                        #pragma unroll
                        for (int k = 0; k < 8; ++k) {
                            po[k] = fmaf(hv0, w0[k], po[k]);
                            po[k] = fmaf(hv1, w1[k], po[k]);
                        }
                    }
                    #pragma unroll
                    for (int k = 0; k < 8; ++k) po[k] = qreduce(po[k]);
                    if (tg == 0) {
                        float* pdst = partO + wh*1024 + jl*8;
                        *(float4*)(pdst)     = make_float4(po[0], po[1], po[2], po[3]);
                        *(float4*)(pdst + 4) = make_float4(po[4], po[5], po[6], po[7]);
                    }
                }
            }
            __syncthreads();
            for (int idx = tid; idx < 1024; idx += 512) {
                float v = oh_b2[idx & 7];
                #pragma unroll
                for (int u = 0; u < 8; ++u) v += partO[u*1024 + idx];
                out[OP_OFF + ((size_t)ti*NN + jt*128 + (idx >> 3))*NOPS + (idx & 7)] = v;
            }
        }
    }
}

// ---------------------------------------------------------------------------
extern "C" void kernel_launch(void* const* d_in, const int* in_sizes, int n_in,
                              void* d_out, int out_size)
{
    const float* obs    = (const float*)d_in[0];
    const float* latent = (const float*)d_in[1];
    const float* query  = (const float*)d_in[2];
    const float* enc_w1 = (const float*)d_in[3];
    const float* enc_b1 = (const float*)d_in[4];
    const float* enc_w2 = (const float*)d_in[5];
    const float* enc_b2 = (const float*)d_in[6];
    const float* upd_w  = (const float*)d_in[7];
    const float* upd_b  = (const float*)d_in[8];
    const float* gru_wi = (const float*)d_in[9];
    const float* gru_bi = (const float*)d_in[10];
    const float* gru_wh = (const float*)d_in[11];
    const float* gru_bh = (const float*)d_in[12];
    const float* eh_w1  = (const float*)d_in[13];
    const float* eh_b1  = (const float*)d_in[14];
    const float* eh_w2  = (const float*)d_in[15];
    const float* eh_b2  = (const float*)d_in[16];
    const float* oh_w1  = (const float*)d_in[17];
    const float* oh_b1  = (const float*)d_in[18];
    const float* oh_w2  = (const float*)d_in[19];
    const float* oh_b2  = (const float*)d_in[20];
    const float* q_w    = (const float*)d_in[21];
    const float* q_b    = (const float*)d_in[22];
    const float* nh_w1  = (const float*)d_in[23];
    const float* nh_b1  = (const float*)d_in[24];
    const float* nh_w2  = (const float*)d_in[25];
    const float* nh_b2  = (const float*)d_in[26];
    float* out = (float*)d_out;

    const int sm1 = SM1_FLOATS * sizeof(float);
    cudaFuncSetAttribute(tok_kernel,  cudaFuncAttributeMaxDynamicSharedMemorySize, sm1);
    cudaFuncSetAttribute(pair_kernel, cudaFuncAttributeMaxDynamicSharedMemorySize, SB_TOTAL);

    tok_kernel<<<TOK/8, 256, sm1>>>(obs, latent, query,
                                    enc_w1, enc_b1, enc_w2, enc_b2,
                                    upd_w, upd_b,
                                    gru_wi, gru_bi, gru_wh, gru_bh,
                                    eh_w1, eh_b1, oh_w1, oh_b1,
                                    q_w, q_b, nh_w1, nh_b1, nh_w2, nh_b2,
                                    out);
    pair_kernel<<<N_CTAS, 512, SB_TOTAL>>>(eh_w1, eh_w2, eh_b2,
                                           oh_w1, oh_w2, oh_b2, out);
}

// round 14
// speedup vs baseline: 1.1118x; 1.1118x over previous
#include <cuda_runtime.h>
#include <math.h>
#include <stdint.h>

// Problem constants
#define BB 4
#define NN 256
#define TOK (BB*NN)        // 1024
#define OBSD 64
#define QDIM 32
#define HH 256
#define DD 128
#define NOPS 8
#define QE 64

// Output layout
#define EDGE_OFF 0
#define OP_OFF   (TOK*NN)                 // 262144
#define NEXT_OFF (OP_OFF + TOK*NN*NOPS)   // 2359296

// Scratch
__device__ float g_lat[TOK * DD];
__device__ float g_EA[TOK * HH];
__device__ float g_EB[TOK * HH];
__device__ float g_OA[TOK * HH];
__device__ float g_OB[TOK * HH];

// ---------------------------------------------------------------------------
// helpers
// ---------------------------------------------------------------------------
__device__ __forceinline__ uint32_t f2tf32(float f) {
    uint32_t r;
    asm("cvt.rna.tf32.f32 %0, %1;" : "=r"(r) : "f"(f));
    return r;
}
__device__ __forceinline__ void mma8(float* c, uint32_t a0, uint32_t a1,
                                     uint32_t a2, uint32_t a3,
                                     uint32_t b0, uint32_t b1) {
    asm volatile(
        "mma.sync.aligned.m16n8k8.row.col.f32.tf32.tf32.f32 "
        "{%0,%1,%2,%3}, {%4,%5,%6,%7}, {%8,%9}, {%0,%1,%2,%3};"
        : "+f"(c[0]), "+f"(c[1]), "+f"(c[2]), "+f"(c[3])
        : "r"(a0), "r"(a1), "r"(a2), "r"(a3), "r"(b0), "r"(b1));
}

// ---------------------------------------------------------------------------
// Kernel 1: per-token pipeline, 8 tokens/block (unchanged; proven).
// ---------------------------------------------------------------------------
#define S_OBS   0
#define S_LATIN (S_OBS+512)
#define S_Q     (S_LATIN+1024)
#define S_H1    (S_Q+256)
#define S_NE    (S_H1+2048)
#define S_UPD   (S_NE+2048)
#define S_GI    (S_UPD+1024)
#define S_GH    (S_GI+3072)
#define S_LAT   (S_GH+3072)
#define S_QE    (S_LAT+1024)
#define S_HID   (S_QE+512)
#define S_RED   (S_HID+2048)
#define SM1_FLOATS (S_RED+256)

__global__ void __launch_bounds__(256)
tok_kernel(const float* __restrict__ obs, const float* __restrict__ latent,
           const float* __restrict__ query,
           const float* __restrict__ enc_w1, const float* __restrict__ enc_b1,
           const float* __restrict__ enc_w2, const float* __restrict__ enc_b2,
           const float* __restrict__ upd_w,  const float* __restrict__ upd_b,
           const float* __restrict__ gru_wi, const float* __restrict__ gru_bi,
           const float* __restrict__ gru_wh, const float* __restrict__ gru_bh,
           const float* __restrict__ eh_w1,  const float* __restrict__ eh_b1,
           const float* __restrict__ oh_w1,  const float* __restrict__ oh_b1,
           const float* __restrict__ q_w,    const float* __restrict__ q_b,
           const float* __restrict__ nh_w1,  const float* __restrict__ nh_b1,
           const float* __restrict__ nh_w2,  const float* __restrict__ nh_b2,
           float* __restrict__ out)
{
    extern __shared__ float sm[];
    const int tid = threadIdx.x;
    const int t0  = blockIdx.x * 8;

    for (int idx = tid; idx < 8*OBSD; idx += 256) sm[S_OBS+idx]   = obs[(size_t)t0*OBSD + idx];
    for (int idx = tid; idx < 8*DD;   idx += 256) sm[S_LATIN+idx] = latent[(size_t)t0*DD + idx];
    sm[S_Q + tid] = query[(size_t)t0*QDIM + tid];
    __syncthreads();

    {
        float acc[8];
        float b = enc_b1[tid];
        #pragma unroll
        for (int t = 0; t < 8; t++) acc[t] = b;
        for (int k = 0; k < OBSD; k++) {
            float w = enc_w1[k*HH + tid];
            #pragma unroll
            for (int t = 0; t < 8; t++) acc[t] = fmaf(sm[S_OBS + t*OBSD + k], w, acc[t]);
        }
        #pragma unroll
        for (int t = 0; t < 8; t++) sm[S_H1 + t*HH + tid] = fmaxf(acc[t], 0.0f);
    }
    __syncthreads();

    {
        float acc[8];
        float b = enc_b2[tid];
        #pragma unroll
        for (int t = 0; t < 8; t++) acc[t] = b;
        for (int k = 0; k < HH; k++) {
            float w = enc_w2[k*HH + tid];
            #pragma unroll
            for (int t = 0; t < 8; t++) acc[t] = fmaf(sm[S_H1 + t*HH + k], w, acc[t]);
        }
        #pragma unroll
        for (int t = 0; t < 8; t++) sm[S_NE + t*HH + tid] = fmaxf(acc[t], 0.0f);
    }
    __syncthreads();

    if (tid < DD) {
        float acc[8];
        float b = upd_b[tid];
        #pragma unroll
        for (int t = 0; t < 8; t++) acc[t] = b;
        for (int k = 0; k < HH; k++) {
            float w = upd_w[k*DD + tid];
            #pragma unroll
            for (int t = 0; t < 8; t++) acc[t] = fmaf(sm[S_NE + t*HH + k], w, acc[t]);
        }
        #pragma unroll
        for (int t = 0; t < 8; t++) sm[S_UPD + t*DD + tid] = acc[t];
    }
    __syncthreads();

    for (int o = tid; o < 3*DD; o += 256) {
        float ai[8], ah[8];
        float bi_ = gru_bi[o], bh_ = gru_bh[o];
        #pragma unroll
        for (int t = 0; t < 8; t++) { ai[t] = bi_; ah[t] = bh_; }
        for (int k = 0; k < DD; k++) {
            float wi = gru_wi[k*(3*DD) + o];
            float wh = gru_wh[k*(3*DD) + o];
            #pragma unroll
            for (int t = 0; t < 8; t++) {
                ai[t] = fmaf(sm[S_UPD   + t*DD + k], wi, ai[t]);
                ah[t] = fmaf(sm[S_LATIN + t*DD + k], wh, ah[t]);
            }
        }
        #pragma unroll
        for (int t = 0; t < 8; t++) { sm[S_GI + t*(3*DD) + o] = ai[t]; sm[S_GH + t*(3*DD) + o] = ah[t]; }
    }
    __syncthreads();

    for (int idx = tid; idx < 8*DD; idx += 256) {
        int t = idx >> 7, d = idx & 127;
        float ir = sm[S_GI + t*(3*DD) + d],        hr = sm[S_GH + t*(3*DD) + d];
        float iz = sm[S_GI + t*(3*DD) + DD + d],   hz = sm[S_GH + t*(3*DD) + DD + d];
        float in_ = sm[S_GI + t*(3*DD) + 2*DD + d], hn = sm[S_GH + t*(3*DD) + 2*DD + d];
        float r = 1.0f / (1.0f + expf(-(ir + hr)));
        float z = 1.0f / (1.0f + expf(-(iz + hz)));
        float nh = tanhf(in_ + r * hn);
        float li = sm[S_LATIN + t*DD + d];
        float l  = (1.0f - z) * nh + z * li;
        sm[S_LAT + t*DD + d] = l;
        g_lat[(size_t)(t0 + t)*DD + d] = l;
    }

    if (tid < QE) {
        float acc[8];
        float b = q_b[tid];
        #pragma unroll
        for (int t = 0; t < 8; t++) acc[t] = b;
        for (int k = 0; k < QDIM; k++) {
            float w = q_w[k*QE + tid];
            #pragma unroll
            for (int t = 0; t < 8; t++) acc[t] = fmaf(sm[S_Q + t*QDIM + k], w, acc[t]);
        }
        #pragma unroll
        for (int t = 0; t < 8; t++) sm[S_QE + t*QE + tid] = fmaxf(acc[t], 0.0f);
    }
    __syncthreads();

    {
        float ea[8], eb[8], oa[8], ob[8];
        float be = eh_b1[tid], bo = oh_b1[tid];
        #pragma unroll
        for (int t = 0; t < 8; t++) { ea[t] = be; eb[t] = 0.f; oa[t] = bo; ob[t] = 0.f; }
        for (int k = 0; k < DD; k++) {
            float wel = eh_w1[k*HH + tid];
            float wer = eh_w1[(DD + k)*HH + tid];
            float wol = oh_w1[k*HH + tid];
            float wor = oh_w1[(DD + k)*HH + tid];
            #pragma unroll
            for (int t = 0; t < 8; t++) {
                float lv = sm[S_LAT + t*DD + k];
                ea[t] = fmaf(lv, wel, ea[t]);
                eb[t] = fmaf(lv, wer, eb[t]);
                oa[t] = fmaf(lv, wol, oa[t]);
                ob[t] = fmaf(lv, wor, ob[t]);
            }
        }
        #pragma unroll
        for (int t = 0; t < 8; t++) {
            size_t p = (size_t)(t0 + t)*HH + tid;
            g_EA[p] = ea[t]; g_EB[p] = eb[t]; g_OA[p] = oa[t]; g_OB[p] = ob[t];
        }
    }

    {
        float acc[8];
        float b = nh_b1[tid];
        #pragma unroll
        for (int t = 0; t < 8; t++) acc[t] = b;
        for (int k = 0; k < DD; k++) {
            float w = nh_w1[k*HH + tid];
            #pragma unroll
            for (int t = 0; t < 8; t++) acc[t] = fmaf(sm[S_LAT + t*DD + k], w, acc[t]);
        }
        for (int k = 0; k < HH; k++) {
            float w = nh_w1[(DD + k)*HH + tid];
            #pragma unroll
            for (int t = 0; t < 8; t++) acc[t] = fmaf(sm[S_NE + t*HH + k], w, acc[t]);
        }
        for (int k = 0; k < QE; k++) {
            float w = nh_w1[(DD + HH + k)*HH + tid];
            #pragma unroll
            for (int t = 0; t < 8; t++) acc[t] = fmaf(sm[S_QE + t*QE + k], w, acc[t]);
        }
        #pragma unroll
        for (int t = 0; t < 8; t++) sm[S_HID + t*HH + tid] = fmaxf(acc[t], 0.0f);
    }
    __syncthreads();

    for (int t = 0; t < 8; t++) {
        sm[S_RED + tid] = sm[S_HID + t*HH + tid] * nh_w2[tid];
        __syncthreads();
        for (int s = 128; s > 0; s >>= 1) {
            if (tid < s) sm[S_RED + tid] += sm[S_RED + tid + s];
            __syncthreads();
        }
        if (tid == 0) out[NEXT_OFF + t0 + t] = sm[S_RED] + nh_b2[0];
        __syncthreads();
    }
}

// ---------------------------------------------------------------------------
// Kernel 2: persistent tf32 mma.sync pair kernel, 256 threads (R7 density +
// R13 permuted-k conflict-free uint2 fragment loads, no register spills).
// 148 CTAs: [0,60) = edge head, [60,148) = op head.
// 8 warps: wj = wid&1 (j half of 64), wh = wid>>1 (h quarter of 64).
// Each warp: 64j x 64h via mma.m16n8k8 (c[4][8][4] = 128 acc regs).
// Permuted k layout: within each 8-k group, k sits at slot (k&3)*2 + ((k>>2)&1)
// so (tg, tg+4) pairs are adjacent words -> ld.shared.v2, conflict-free per
// half-warp (gid = lane>>2; half-warp covers gid 0..3 -> 32 distinct banks).
// ---------------------------------------------------------------------------
#define DSTRIDE 136                   // words/row
#define SB_D    0                     // 128*136*4 = 69632 B (aliased by partO 64KB)
#define SB_W    69632                 // 16*2048*4 = 131072 B  [ks][h*8+slot]
#define SB_W2   (SB_W + 131072)       // 200704: 2048 f
#define SB_EA   (SB_W2 + 8192)        // 208896: 256 f
#define SB_REDB (SB_EA + 1024)        // 209920: 2048 f (edge partials 16x128)
#define SB_LATI (SB_REDB + 8192)      // 218112: 128 f
#define SB_TOTAL (SB_LATI + 512)      // 218624 B

#define N_EDGE_CTAS 60
#define N_CTAS 148

__global__ void __launch_bounds__(256, 1)
pair_kernel(const float* __restrict__ eh_w1, const float* __restrict__ eh_w2,
            const float* __restrict__ eh_b2,
            const float* __restrict__ oh_w1, const float* __restrict__ oh_w2,
            const float* __restrict__ oh_b2,
            float* __restrict__ out)
{
    extern __shared__ char smraw[];
    uint32_t* dD    = (uint32_t*)(smraw + SB_D);
    uint32_t* dW    = (uint32_t*)(smraw + SB_W);
    float*    smW2  = (float*)(smraw + SB_W2);
    float*    smEA  = (float*)(smraw + SB_EA);
    float*    smRED = (float*)(smraw + SB_REDB);
    float*    smLAT = (float*)(smraw + SB_LATI);
    float*    partO = (float*)(smraw + SB_D);   // aliases D (dead after mainloop+sync)

    const int tid  = threadIdx.x;
    const int wid  = tid >> 5;      // 0..7
    const int lane = tid & 31;
    const int gid  = lane >> 2;     // 0..7
    const int tg   = lane & 3;      // 0..3
    const int wj   = wid & 1;       // j half
    const int wh   = wid >> 1;      // 0..3 : h quarter of 64
    const int j0   = wj * 64;
    const int h0   = wh * 64;

    int head, pos, npos;
    if (blockIdx.x < N_EDGE_CTAS) { head = 0; pos = blockIdx.x;               npos = N_EDGE_CTAS; }
    else                          { head = 1; pos = blockIdx.x - N_EDGE_CTAS; npos = N_CTAS - N_EDGE_CTAS; }

    // ---- stage W_abs (tf32, permuted) once per CTA ----
    {
        const float* Wsrc = (head ? oh_w1 : eh_w1) + (size_t)(2*DD)*HH;
        for (int idx = tid; idx < DD*HH; idx += 256) {
            int k = idx >> 8, h = idx & 255;
            dW[(k>>3)*2048 + h*8 + (k&3)*2 + ((k>>2)&1)] = f2tf32(Wsrc[idx]);
        }
        if (head == 0) { if (tid < 256) smW2[tid] = eh_w2[tid]; }
        else           { for (int idx = tid; idx < HH*NOPS; idx += 256) smW2[idx] = oh_w2[idx]; }
    }

    const float* XA = head ? g_OA : g_EA;
    const float* XB = head ? g_OB : g_EB;

    // per-lane D-build store slot: lane owns k = lane + 32q
    const int dslot = (lane >> 3)*8 + (lane & 3)*2 + ((lane >> 2) & 1);

    for (int g = pos; g < 2048; g += npos) {
        const int b = g >> 9, i = (g >> 1) & 255, jt = g & 1;
        const int ti = b*NN + i;
        const int jbase = b*NN + jt*128;

        __syncthreads();   // prev epilogue done before overwriting smEA/smLAT/D
        if (tid < 128) smLAT[tid] = g_lat[(size_t)ti*DD + tid];
        smEA[tid] = XA[(size_t)ti*HH + tid];
        __syncthreads();

        // ---- build D[j][k] = tf32(|lat_i - lat_j|), permuted k layout ----
        {
            float li4[4];
            #pragma unroll
            for (int q = 0; q < 4; ++q) li4[q] = smLAT[lane + 32*q];
            #pragma unroll
            for (int jj = 0; jj < 16; ++jj) {
                int j = wid*16 + jj;
                const float* lrow = g_lat + (size_t)(jbase + j)*DD;
                uint32_t* dst = dD + j*DSTRIDE + dslot;
                #pragma unroll
                for (int q = 0; q < 4; ++q)
                    dst[q*32] = f2tf32(fabsf(li4[q] - lrow[lane + 32*q]));
            }
        }
        __syncthreads();

        // ---- mma phase: hidden[64j x 64h] per warp ----
        float c[4][8][4];
        #pragma unroll
        for (int mt = 0; mt < 4; ++mt)
            #pragma unroll
            for (int nt = 0; nt < 8; ++nt)
                #pragma unroll
                for (int q = 0; q < 4; ++q) c[mt][nt][q] = 0.0f;

        const uint32_t* Ab = dD + (j0 + gid)*DSTRIDE + 2*tg;
        const uint32_t* Bb = dW + (h0 + gid)*8 + 2*tg;

        #pragma unroll 2
        for (int ks = 0; ks < 16; ++ks) {
            uint2 av[4], aw[4], bv[8];
            #pragma unroll
            for (int mt = 0; mt < 4; ++mt) {
                av[mt] = *(const uint2*)(Ab + (mt*16)*DSTRIDE + ks*8);
                aw[mt] = *(const uint2*)(Ab + (mt*16+8)*DSTRIDE + ks*8);
            }
            #pragma unroll
            for (int nt = 0; nt < 8; ++nt)
                bv[nt] = *(const uint2*)(Bb + ks*2048 + nt*64);
            #pragma unroll
            for (int nt = 0; nt < 8; ++nt)
                #pragma unroll
                for (int mt = 0; mt < 4; ++mt)
                    mma8(c[mt][nt], av[mt].x, aw[mt].x, av[mt].y, aw[mt].y,
                         bv[nt].x, bv[nt].y);
        }
        __syncthreads();   // all warps done reading D before partO aliases it

        // ---- epilogue ----
        if (head == 0) {
            #pragma unroll
            for (int mt = 0; mt < 4; ++mt) {
                #pragma unroll
                for (int rh = 0; rh < 2; ++rh) {
                    int jl = j0 + mt*16 + gid + rh*8;
                    const float* ebrow = XB + (size_t)(jbase + jl)*HH;
                    float part = 0.0f;
                    #pragma unroll
                    for (int nt = 0; nt < 8; ++nt) {
                        int ha = h0 + nt*8 + 2*tg;
                        float2 eb = *(const float2*)(ebrow + ha);
                        float hv0 = fmaxf(c[mt][nt][rh*2+0] + smEA[ha]   + eb.x, 0.0f);
                        float hv1 = fmaxf(c[mt][nt][rh*2+1] + smEA[ha+1] + eb.y, 0.0f);
                        part = fmaf(hv0, smW2[ha],   part);
                        part = fmaf(hv1, smW2[ha+1], part);
                    }
                    smRED[(wh*4 + tg)*128 + jl] = part;
                }
            }
            __syncthreads();
            if (tid < 128) {
                float v = eh_b2[0];
                #pragma unroll
                for (int u = 0; u < 16; ++u) v += smRED[u*128 + tid];
                int jg = jt*128 + tid;
                if (jg == i) v = -8.0f;
                out[EDGE_OFF + (size_t)ti*NN + jg] = v;
            }
        } else {
            #pragma unroll
            for (int mt = 0; mt < 4; ++mt) {
                #pragma unroll
                for (int rh = 0; rh < 2; ++rh) {
                    int jl = j0 + mt*16 + gid + rh*8;
                    const float* obrow = XB + (size_t)(jbase + jl)*HH;
                    float po[8];
                    #pragma unroll
                    for (int k = 0; k < 8; ++k) po[k] = 0.0f;
                    #pragma unroll
                    for (int nt = 0; nt < 8; ++nt) {
                        int ha = h0 + nt*8 + 2*tg;
                        float2 ob = *(const float2*)(obrow + ha);
                        float hv0 = fmaxf(c[mt][nt][rh*2+0] + smEA[ha]   + ob.x, 0.0f);
                        float hv1 = fmaxf(c[mt][nt][rh*2+1] + smEA[ha+1] + ob.y, 0.0f);
                        const float* w0 = smW2 + ha*8;
                        const float* w1 = smW2 + (ha+1)*8;
                        #pragma unroll
                        for (int k = 0; k < 8; ++k) {
                            po[k] = fmaf(hv0, w0[k], po[k]);
                            po[k] = fmaf(hv1, w1[k], po[k]);
                        }
                    }
                    float* pdst = partO + (wh*4 + tg)*1024 + jl*8;
                    *(float4*)(pdst)     = make_float4(po[0], po[1], po[2], po[3]);
                    *(float4*)(pdst + 4) = make_float4(po[4], po[5], po[6], po[7]);
                }
            }
            __syncthreads();
            for (int idx = tid; idx < 1024; idx += 256) {
                float v = oh_b2[idx & 7];
                #pragma unroll
                for (int u = 0; u < 16; ++u) v += partO[u*1024 + idx];
                out[OP_OFF + ((size_t)ti*NN + jt*128 + (idx >> 3))*NOPS + (idx & 7)] = v;
            }
        }
    }
}

// ---------------------------------------------------------------------------
extern "C" void kernel_launch(void* const* d_in, const int* in_sizes, int n_in,
                              void* d_out, int out_size)
{
    const float* obs    = (const float*)d_in[0];
    const float* latent = (const float*)d_in[1];
    const float* query  = (const float*)d_in[2];
    const float* enc_w1 = (const float*)d_in[3];
    const float* enc_b1 = (const float*)d_in[4];
    const float* enc_w2 = (const float*)d_in[5];
    const float* enc_b2 = (const float*)d_in[6];
    const float* upd_w  = (const float*)d_in[7];
    const float* upd_b  = (const float*)d_in[8];
    const float* gru_wi = (const float*)d_in[9];
    const float* gru_bi = (const float*)d_in[10];
    const float* gru_wh = (const float*)d_in[11];
    const float* gru_bh = (const float*)d_in[12];
    const float* eh_w1  = (const float*)d_in[13];
    const float* eh_b1  = (const float*)d_in[14];
    const float* eh_w2  = (const float*)d_in[15];
    const float* eh_b2  = (const float*)d_in[16];
    const float* oh_w1  = (const float*)d_in[17];
    const float* oh_b1  = (const float*)d_in[18];
    const float* oh_w2  = (const float*)d_in[19];
    const float* oh_b2  = (const float*)d_in[20];
    const float* q_w    = (const float*)d_in[21];
    const float* q_b    = (const float*)d_in[22];
    const float* nh_w1  = (const float*)d_in[23];
    const float* nh_b1  = (const float*)d_in[24];
    const float* nh_w2  = (const float*)d_in[25];
    const float* nh_b2  = (const float*)d_in[26];
    float* out = (float*)d_out;

    const int sm1 = SM1_FLOATS * sizeof(float);
    cudaFuncSetAttribute(tok_kernel,  cudaFuncAttributeMaxDynamicSharedMemorySize, sm1);
    cudaFuncSetAttribute(pair_kernel, cudaFuncAttributeMaxDynamicSharedMemorySize, SB_TOTAL);

    tok_kernel<<<TOK/8, 256, sm1>>>(obs, latent, query,
                                    enc_w1, enc_b1, enc_w2, enc_b2,
                                    upd_w, upd_b,
                                    gru_wi, gru_bi, gru_wh, gru_bh,
                                    eh_w1, eh_b1, oh_w1, oh_b1,
                                    q_w, q_b, nh_w1, nh_b1, nh_w2, nh_b2,
                                    out);
    pair_kernel<<<N_CTAS, 256, SB_TOTAL>>>(eh_w1, eh_w2, eh_b2,
                                           oh_w1, oh_w2, oh_b2, out);
}

// round 15
// speedup vs baseline: 1.2501x; 1.1244x over previous
#include <cuda_runtime.h>
#include <math.h>
#include <stdint.h>

// Problem constants
#define BB 4
#define NN 256
#define TOK (BB*NN)        // 1024
#define OBSD 64
#define QDIM 32
#define HH 256
#define DD 128
#define NOPS 8
#define QE 64

// Output layout
#define EDGE_OFF 0
#define OP_OFF   (TOK*NN)                 // 262144
#define NEXT_OFF (OP_OFF + TOK*NN*NOPS)   // 2359296

// Scratch
__device__ float g_lat[TOK * DD];
__device__ float g_EA[TOK * HH];
__device__ float g_EB[TOK * HH];
__device__ float g_OA[TOK * HH];
__device__ float g_OB[TOK * HH];

// ---------------------------------------------------------------------------
// helpers
// ---------------------------------------------------------------------------
__device__ __forceinline__ uint32_t f2tf32(float f) {
    uint32_t r;
    asm("cvt.rna.tf32.f32 %0, %1;" : "=r"(r) : "f"(f));
    return r;
}
__device__ __forceinline__ void mma8(float* c, uint32_t a0, uint32_t a1,
                                     uint32_t a2, uint32_t a3,
                                     uint32_t b0, uint32_t b1) {
    asm volatile(
        "mma.sync.aligned.m16n8k8.row.col.f32.tf32.tf32.f32 "
        "{%0,%1,%2,%3}, {%4,%5,%6,%7}, {%8,%9}, {%0,%1,%2,%3};"
        : "+f"(c[0]), "+f"(c[1]), "+f"(c[2]), "+f"(c[3])
        : "r"(a0), "r"(a1), "r"(a2), "r"(a3), "r"(b0), "r"(b1));
}

// ---------------------------------------------------------------------------
// Kernel 1: per-token pipeline, 8 tokens/block (unchanged; proven).
// ---------------------------------------------------------------------------
#define S_OBS   0
#define S_LATIN (S_OBS+512)
#define S_Q     (S_LATIN+1024)
#define S_H1    (S_Q+256)
#define S_NE    (S_H1+2048)
#define S_UPD   (S_NE+2048)
#define S_GI    (S_UPD+1024)
#define S_GH    (S_GI+3072)
#define S_LAT   (S_GH+3072)
#define S_QE    (S_LAT+1024)
#define S_HID   (S_QE+512)
#define S_RED   (S_HID+2048)
#define SM1_FLOATS (S_RED+256)

__global__ void __launch_bounds__(256)
tok_kernel(const float* __restrict__ obs, const float* __restrict__ latent,
           const float* __restrict__ query,
           const float* __restrict__ enc_w1, const float* __restrict__ enc_b1,
           const float* __restrict__ enc_w2, const float* __restrict__ enc_b2,
           const float* __restrict__ upd_w,  const float* __restrict__ upd_b,
           const float* __restrict__ gru_wi, const float* __restrict__ gru_bi,
           const float* __restrict__ gru_wh, const float* __restrict__ gru_bh,
           const float* __restrict__ eh_w1,  const float* __restrict__ eh_b1,
           const float* __restrict__ oh_w1,  const float* __restrict__ oh_b1,
           const float* __restrict__ q_w,    const float* __restrict__ q_b,
           const float* __restrict__ nh_w1,  const float* __restrict__ nh_b1,
           const float* __restrict__ nh_w2,  const float* __restrict__ nh_b2,
           float* __restrict__ out)
{
    extern __shared__ float sm[];
    const int tid = threadIdx.x;
    const int t0  = blockIdx.x * 8;

    for (int idx = tid; idx < 8*OBSD; idx += 256) sm[S_OBS+idx]   = obs[(size_t)t0*OBSD + idx];
    for (int idx = tid; idx < 8*DD;   idx += 256) sm[S_LATIN+idx] = latent[(size_t)t0*DD + idx];
    sm[S_Q + tid] = query[(size_t)t0*QDIM + tid];
    __syncthreads();

    {
        float acc[8];
        float b = enc_b1[tid];
        #pragma unroll
        for (int t = 0; t < 8; t++) acc[t] = b;
        for (int k = 0; k < OBSD; k++) {
            float w = enc_w1[k*HH + tid];
            #pragma unroll
            for (int t = 0; t < 8; t++) acc[t] = fmaf(sm[S_OBS + t*OBSD + k], w, acc[t]);
        }
        #pragma unroll
        for (int t = 0; t < 8; t++) sm[S_H1 + t*HH + tid] = fmaxf(acc[t], 0.0f);
    }
    __syncthreads();

    {
        float acc[8];
        float b = enc_b2[tid];
        #pragma unroll
        for (int t = 0; t < 8; t++) acc[t] = b;
        for (int k = 0; k < HH; k++) {
            float w = enc_w2[k*HH + tid];
            #pragma unroll
            for (int t = 0; t < 8; t++) acc[t] = fmaf(sm[S_H1 + t*HH + k], w, acc[t]);
        }
        #pragma unroll
        for (int t = 0; t < 8; t++) sm[S_NE + t*HH + tid] = fmaxf(acc[t], 0.0f);
    }
    __syncthreads();

    if (tid < DD) {
        float acc[8];
        float b = upd_b[tid];
        #pragma unroll
        for (int t = 0; t < 8; t++) acc[t] = b;
        for (int k = 0; k < HH; k++) {
            float w = upd_w[k*DD + tid];
            #pragma unroll
            for (int t = 0; t < 8; t++) acc[t] = fmaf(sm[S_NE + t*HH + k], w, acc[t]);
        }
        #pragma unroll
        for (int t = 0; t < 8; t++) sm[S_UPD + t*DD + tid] = acc[t];
    }
    __syncthreads();

    for (int o = tid; o < 3*DD; o += 256) {
        float ai[8], ah[8];
        float bi_ = gru_bi[o], bh_ = gru_bh[o];
        #pragma unroll
        for (int t = 0; t < 8; t++) { ai[t] = bi_; ah[t] = bh_; }
        for (int k = 0; k < DD; k++) {
            float wi = gru_wi[k*(3*DD) + o];
            float wh = gru_wh[k*(3*DD) + o];
            #pragma unroll
            for (int t = 0; t < 8; t++) {
                ai[t] = fmaf(sm[S_UPD   + t*DD + k], wi, ai[t]);
                ah[t] = fmaf(sm[S_LATIN + t*DD + k], wh, ah[t]);
            }
        }
        #pragma unroll
        for (int t = 0; t < 8; t++) { sm[S_GI + t*(3*DD) + o] = ai[t]; sm[S_GH + t*(3*DD) + o] = ah[t]; }
    }
    __syncthreads();

    for (int idx = tid; idx < 8*DD; idx += 256) {
        int t = idx >> 7, d = idx & 127;
        float ir = sm[S_GI + t*(3*DD) + d],        hr = sm[S_GH + t*(3*DD) + d];
        float iz = sm[S_GI + t*(3*DD) + DD + d],   hz = sm[S_GH + t*(3*DD) + DD + d];
        float in_ = sm[S_GI + t*(3*DD) + 2*DD + d], hn = sm[S_GH + t*(3*DD) + 2*DD + d];
        float r = 1.0f / (1.0f + expf(-(ir + hr)));
        float z = 1.0f / (1.0f + expf(-(iz + hz)));
        float nh = tanhf(in_ + r * hn);
        float li = sm[S_LATIN + t*DD + d];
        float l  = (1.0f - z) * nh + z * li;
        sm[S_LAT + t*DD + d] = l;
        g_lat[(size_t)(t0 + t)*DD + d] = l;
    }

    if (tid < QE) {
        float acc[8];
        float b = q_b[tid];
        #pragma unroll
        for (int t = 0; t < 8; t++) acc[t] = b;
        for (int k = 0; k < QDIM; k++) {
            float w = q_w[k*QE + tid];
            #pragma unroll
            for (int t = 0; t < 8; t++) acc[t] = fmaf(sm[S_Q + t*QDIM + k], w, acc[t]);
        }
        #pragma unroll
        for (int t = 0; t < 8; t++) sm[S_QE + t*QE + tid] = fmaxf(acc[t], 0.0f);
    }
    __syncthreads();

    {
        float ea[8], eb[8], oa[8], ob[8];
        float be = eh_b1[tid], bo = oh_b1[tid];
        #pragma unroll
        for (int t = 0; t < 8; t++) { ea[t] = be; eb[t] = 0.f; oa[t] = bo; ob[t] = 0.f; }
        for (int k = 0; k < DD; k++) {
            float wel = eh_w1[k*HH + tid];
            float wer = eh_w1[(DD + k)*HH + tid];
            float wol = oh_w1[k*HH + tid];
            float wor = oh_w1[(DD + k)*HH + tid];
            #pragma unroll
            for (int t = 0; t < 8; t++) {
                float lv = sm[S_LAT + t*DD + k];
                ea[t] = fmaf(lv, wel, ea[t]);
                eb[t] = fmaf(lv, wer, eb[t]);
                oa[t] = fmaf(lv, wol, oa[t]);
                ob[t] = fmaf(lv, wor, ob[t]);
            }
        }
        #pragma unroll
        for (int t = 0; t < 8; t++) {
            size_t p = (size_t)(t0 + t)*HH + tid;
            g_EA[p] = ea[t]; g_EB[p] = eb[t]; g_OA[p] = oa[t]; g_OB[p] = ob[t];
        }
    }

    {
        float acc[8];
        float b = nh_b1[tid];
        #pragma unroll
        for (int t = 0; t < 8; t++) acc[t] = b;
        for (int k = 0; k < DD; k++) {
            float w = nh_w1[k*HH + tid];
            #pragma unroll
            for (int t = 0; t < 8; t++) acc[t] = fmaf(sm[S_LAT + t*DD + k], w, acc[t]);
        }
        for (int k = 0; k < HH; k++) {
            float w = nh_w1[(DD + k)*HH + tid];
            #pragma unroll
            for (int t = 0; t < 8; t++) acc[t] = fmaf(sm[S_NE + t*HH + k], w, acc[t]);
        }
        for (int k = 0; k < QE; k++) {
            float w = nh_w1[(DD + HH + k)*HH + tid];
            #pragma unroll
            for (int t = 0; t < 8; t++) acc[t] = fmaf(sm[S_QE + t*QE + k], w, acc[t]);
        }
        #pragma unroll
        for (int t = 0; t < 8; t++) sm[S_HID + t*HH + tid] = fmaxf(acc[t], 0.0f);
    }
    __syncthreads();

    for (int t = 0; t < 8; t++) {
        sm[S_RED + tid] = sm[S_HID + t*HH + tid] * nh_w2[tid];
        __syncthreads();
        for (int s = 128; s > 0; s >>= 1) {
            if (tid < s) sm[S_RED + tid] += sm[S_RED + tid + s];
            __syncthreads();
        }
        if (tid == 0) out[NEXT_OFF + t0 + t] = sm[S_RED] + nh_b2[0];
        __syncthreads();
    }
}

// ---------------------------------------------------------------------------
// Kernel 2: persistent tf32 mma.sync pair kernel, 256 threads.
// R7 structure (scalar conflict-free LDS, plain layouts) + manual 2-stage
// software-pipelined fragment prefetch with statically named double buffers
// (A0/B0, A1/B1) to bound peak register demand (~200 regs -> no spills).
// 148 CTAs: [0,60) = edge head, [60,148) = op head.
// 8 warps: wj = wid&1 (j half of 64), wh = wid>>1 (h quarter of 64).
// Each warp: 64j x 64h via mma.m16n8k8 (c[4][8][4] = 128 acc regs).
// ---------------------------------------------------------------------------
#define DSTRIDE 132   // floats per D row (pad: conflict-free A frags)
#define WSTRIDE 264   // floats per W row (pad: conflict-free B frags)
#define SB_D    0                     // 128*132*4 = 67584 B (reused as partO)
#define SB_W    67584                 // 128*264*4 = 135168 B
#define SB_W2   (SB_W + 135168)       // 202752: 2048 f
#define SB_EA   (SB_W2 + 8192)        // 210944: 256 f
#define SB_REDB (SB_EA + 1024)        // 211968: 2048 f (edge partials 16x128)
#define SB_LATI (SB_REDB + 8192)      // 220160: 128 f
#define SB_TOTAL (SB_LATI + 512)      // 220672 B

#define N_EDGE_CTAS 60
#define N_CTAS 148

#define LOAD_FRAGS(A, Bv, ks) do {                                          \
    _Pragma("unroll")                                                       \
    for (int mt_ = 0; mt_ < 4; ++mt_) {                                     \
        const uint32_t* ap_ = Ab + mt_*16*DSTRIDE + (ks)*8;                 \
        A[mt_][0] = ap_[0];                                                 \
        A[mt_][1] = ap_[8*DSTRIDE];                                         \
        A[mt_][2] = ap_[4];                                                 \
        A[mt_][3] = ap_[8*DSTRIDE + 4];                                     \
    }                                                                       \
    {                                                                       \
        const uint32_t* bp_ = Bb + (ks)*8*WSTRIDE;                          \
        _Pragma("unroll")                                                   \
        for (int nt_ = 0; nt_ < 8; ++nt_) {                                 \
            Bv[nt_][0] = bp_[nt_*8];                                        \
            Bv[nt_][1] = bp_[4*WSTRIDE + nt_*8];                            \
        }                                                                   \
    }                                                                       \
} while (0)

#define MMA_ALL(A, Bv)                                                      \
    _Pragma("unroll")                                                       \
    for (int nt_ = 0; nt_ < 8; ++nt_)                                       \
        _Pragma("unroll")                                                   \
        for (int mt_ = 0; mt_ < 4; ++mt_)                                   \
            mma8(c[mt_][nt_], A[mt_][0], A[mt_][1], A[mt_][2], A[mt_][3],   \
                 Bv[nt_][0], Bv[nt_][1]);

__global__ void __launch_bounds__(256, 1)
pair_kernel(const float* __restrict__ eh_w1, const float* __restrict__ eh_w2,
            const float* __restrict__ eh_b2,
            const float* __restrict__ oh_w1, const float* __restrict__ oh_w2,
            const float* __restrict__ oh_b2,
            float* __restrict__ out)
{
    extern __shared__ char smraw[];
    uint32_t* dD    = (uint32_t*)(smraw + SB_D);
    uint32_t* dW    = (uint32_t*)(smraw + SB_W);
    float*    smW2  = (float*)(smraw + SB_W2);
    float*    smEA  = (float*)(smraw + SB_EA);
    float*    smRED = (float*)(smraw + SB_REDB);
    float*    smLAT = (float*)(smraw + SB_LATI);
    float*    partO = (float*)(smraw + SB_D);   // aliases D (dead after mainloop+sync)

    const int tid  = threadIdx.x;
    const int wid  = tid >> 5;
    const int lane = tid & 31;
    const int gid  = lane >> 2;     // 0..7
    const int tg   = lane & 3;      // 0..3
    const int wj   = wid & 1;       // j half
    const int wh   = wid >> 1;      // h quarter
    const int j0   = wj * 64;
    const int h0   = wh * 64;

    int head, pos, npos;
    if (blockIdx.x < N_EDGE_CTAS) { head = 0; pos = blockIdx.x;               npos = N_EDGE_CTAS; }
    else                          { head = 1; pos = blockIdx.x - N_EDGE_CTAS; npos = N_CTAS - N_EDGE_CTAS; }

    // ---- stage W_abs (tf32) once per CTA ----
    {
        const float* Wsrc = (head ? oh_w1 : eh_w1) + (size_t)(2*DD)*HH;
        for (int idx = tid; idx < DD*HH; idx += 256) {
            int k = idx >> 8, h = idx & 255;
            dW[k*WSTRIDE + h] = f2tf32(Wsrc[idx]);
        }
        if (head == 0) { if (tid < 256) smW2[tid] = eh_w2[tid]; }
        else           { for (int idx = tid; idx < HH*NOPS; idx += 256) smW2[idx] = oh_w2[idx]; }
    }

    const float* XA = head ? g_OA : g_EA;
    const float* XB = head ? g_OB : g_EB;

    for (int g = pos; g < 2048; g += npos) {
        const int b = g >> 9, i = (g >> 1) & 255, jt = g & 1;
        const int ti = b*NN + i;
        const int jbase = b*NN + jt*128;

        __syncthreads();   // prev epilogue done before overwriting smEA/smLAT/D
        if (tid < 128) smLAT[tid] = g_lat[(size_t)ti*DD + tid];
        smEA[tid] = XA[(size_t)ti*HH + tid];
        __syncthreads();

        // ---- build D[j][k] = tf32(|lat_i - lat_j|), row-major stride 132 ----
        {
            const float4 li = ((const float4*)smLAT)[lane];
            #pragma unroll
            for (int jj = 0; jj < 16; ++jj) {
                int j = wid*16 + jj;
                float4 lj = ((const float4*)(g_lat + (size_t)(jbase + j)*DD))[lane];
                uint4 dv;
                dv.x = f2tf32(fabsf(li.x - lj.x));
                dv.y = f2tf32(fabsf(li.y - lj.y));
                dv.z = f2tf32(fabsf(li.z - lj.z));
                dv.w = f2tf32(fabsf(li.w - lj.w));
                *(uint4*)(dD + j*DSTRIDE + lane*4) = dv;
            }
        }
        __syncthreads();

        // ---- mma phase: hidden[64j x 64h] per warp, 2-stage pipeline ----
        float c[4][8][4];
        #pragma unroll
        for (int mt = 0; mt < 4; ++mt)
            #pragma unroll
            for (int nt = 0; nt < 8; ++nt)
                #pragma unroll
                for (int q = 0; q < 4; ++q) c[mt][nt][q] = 0.0f;

        const uint32_t* Ab = dD + (j0 + gid)*DSTRIDE + tg;
        const uint32_t* Bb = dW + tg*WSTRIDE + h0 + gid;

        uint32_t A0[4][4], B0[8][2], A1[4][4], B1[8][2];
        LOAD_FRAGS(A0, B0, 0);
        #pragma unroll
        for (int ks = 0; ks < 16; ks += 2) {
            if (ks + 1 < 16) LOAD_FRAGS(A1, B1, ks + 1);
            MMA_ALL(A0, B0);
            if (ks + 2 < 16) LOAD_FRAGS(A0, B0, ks + 2);
            if (ks + 1 < 16) MMA_ALL(A1, B1);
        }
        __syncthreads();   // all warps done reading D before partO aliases it

        // ---- epilogue ----
        if (head == 0) {
            #pragma unroll
            for (int mt = 0; mt < 4; ++mt) {
                #pragma unroll
                for (int rh = 0; rh < 2; ++rh) {
                    int jl = j0 + mt*16 + gid + rh*8;
                    const float* ebrow = XB + (size_t)(jbase + jl)*HH;
                    float part = 0.0f;
                    #pragma unroll
                    for (int nt = 0; nt < 8; ++nt) {
                        int ha = h0 + nt*8 + 2*tg;
                        float2 eb = *(const float2*)(ebrow + ha);
                        float hv0 = fmaxf(c[mt][nt][rh*2+0] + smEA[ha]   + eb.x, 0.0f);
                        float hv1 = fmaxf(c[mt][nt][rh*2+1] + smEA[ha+1] + eb.y, 0.0f);
                        part = fmaf(hv0, smW2[ha],   part);
                        part = fmaf(hv1, smW2[ha+1], part);
                    }
                    smRED[(wh*4 + tg)*128 + jl] = part;
                }
            }
            __syncthreads();
            if (tid < 128) {
                float v = eh_b2[0];
                #pragma unroll
                for (int u = 0; u < 16; ++u) v += smRED[u*128 + tid];
                int jg = jt*128 + tid;
                if (jg == i) v = -8.0f;
                out[EDGE_OFF + (size_t)ti*NN + jg] = v;
            }
        } else {
            #pragma unroll
            for (int mt = 0; mt < 4; ++mt) {
                #pragma unroll
                for (int rh = 0; rh < 2; ++rh) {
                    int jl = j0 + mt*16 + gid + rh*8;
                    const float* obrow = XB + (size_t)(jbase + jl)*HH;
                    float po[8];
                    #pragma unroll
                    for (int k = 0; k < 8; ++k) po[k] = 0.0f;
                    #pragma unroll
                    for (int nt = 0; nt < 8; ++nt) {
                        int ha = h0 + nt*8 + 2*tg;
                        float2 ob = *(const float2*)(obrow + ha);
                        float hv0 = fmaxf(c[mt][nt][rh*2+0] + smEA[ha]   + ob.x, 0.0f);
                        float hv1 = fmaxf(c[mt][nt][rh*2+1] + smEA[ha+1] + ob.y, 0.0f);
                        const float* w0 = smW2 + ha*8;
                        const float* w1 = smW2 + (ha+1)*8;
                        #pragma unroll
                        for (int k = 0; k < 8; ++k) {
                            po[k] = fmaf(hv0, w0[k], po[k]);
                            po[k] = fmaf(hv1, w1[k], po[k]);
                        }
                    }
                    float* pdst = partO + (wh*4 + tg)*1024 + jl*8;
                    *(float4*)(pdst)     = make_float4(po[0], po[1], po[2], po[3]);
                    *(float4*)(pdst + 4) = make_float4(po[4], po[5], po[6], po[7]);
                }
            }
            __syncthreads();
            for (int idx = tid; idx < 1024; idx += 256) {
                float v = oh_b2[idx & 7];
                #pragma unroll
                for (int u = 0; u < 16; ++u) v += partO[u*1024 + idx];
                out[OP_OFF + ((size_t)ti*NN + jt*128 + (idx >> 3))*NOPS + (idx & 7)] = v;
            }
        }
    }
}

// ---------------------------------------------------------------------------
extern "C" void kernel_launch(void* const* d_in, const int* in_sizes, int n_in,
                              void* d_out, int out_size)
{
    const float* obs    = (const float*)d_in[0];
    const float* latent = (const float*)d_in[1];
    const float* query  = (const float*)d_in[2];
    const float* enc_w1 = (const float*)d_in[3];
    const float* enc_b1 = (const float*)d_in[4];
    const float* enc_w2 = (const float*)d_in[5];
    const float* enc_b2 = (const float*)d_in[6];
    const float* upd_w  = (const float*)d_in[7];
    const float* upd_b  = (const float*)d_in[8];
    const float* gru_wi = (const float*)d_in[9];
    const float* gru_bi = (const float*)d_in[10];
    const float* gru_wh = (const float*)d_in[11];
    const float* gru_bh = (const float*)d_in[12];
    const float* eh_w1  = (const float*)d_in[13];
    const float* eh_b1  = (const float*)d_in[14];
    const float* eh_w2  = (const float*)d_in[15];
    const float* eh_b2  = (const float*)d_in[16];
    const float* oh_w1  = (const float*)d_in[17];
    const float* oh_b1  = (const float*)d_in[18];
    const float* oh_w2  = (const float*)d_in[19];
    const float* oh_b2  = (const float*)d_in[20];
    const float* q_w    = (const float*)d_in[21];
    const float* q_b    = (const float*)d_in[22];
    const float* nh_w1  = (const float*)d_in[23];
    const float* nh_b1  = (const float*)d_in[24];
    const float* nh_w2  = (const float*)d_in[25];
    const float* nh_b2  = (const float*)d_in[26];
    float* out = (float*)d_out;

    const int sm1 = SM1_FLOATS * sizeof(float);
    cudaFuncSetAttribute(tok_kernel,  cudaFuncAttributeMaxDynamicSharedMemorySize, sm1);
    cudaFuncSetAttribute(pair_kernel, cudaFuncAttributeMaxDynamicSharedMemorySize, SB_TOTAL);

    tok_kernel<<<TOK/8, 256, sm1>>>(obs, latent, query,
                                    enc_w1, enc_b1, enc_w2, enc_b2,
                                    upd_w, upd_b,
                                    gru_wi, gru_bi, gru_wh, gru_bh,
                                    eh_w1, eh_b1, oh_w1, oh_b1,
                                    q_w, q_b, nh_w1, nh_b1, nh_w2, nh_b2,
                                    out);
    pair_kernel<<<N_CTAS, 256, SB_TOTAL>>>(eh_w1, eh_w2, eh_b2,
                                           oh_w1, oh_w2, oh_b2, out);
}